// round 2
// baseline (speedup 1.0000x reference)
#include <cuda_runtime.h>
#include <math.h>

#define NN 100000
#define EE 3200000
#define EP (EE + NN)
#define GG 1024
#define HC 64
#define NBLK ((NN + 127) / 128)

// ---------------- device scratch (no allocations allowed) ----------------
__device__ int   g_stride;        // 1 if indices are int32, 2 if int64
__device__ int   g_deg[NN];
__device__ int   g_rowptr[NN + 1];
__device__ int   g_cursor[NN];
__device__ int   g_csr[EP];
__device__ int   g_part[NBLK];
__device__ int   g_pscan[NBLK];
__device__ float g_hA[NN * HC];   // pre-aggregation features (x@W)
__device__ float g_hB[NN * HC];   // post-aggregation (elu) features
__device__ float g_asrc[NN * 4];
__device__ float g_adst[NN * 4];
__device__ float g_pool[GG * HC];
__device__ int   g_cnt[GG];

__device__ __forceinline__ int clampN(int v) {
    return v < 0 ? 0 : (v >= NN ? NN - 1 : v);
}

// ---------------- dtype probe: int32 vs int64 index buffers ----------------
__global__ void k_detect(const int* __restrict__ ei32) {
    __shared__ int any;
    if (threadIdx.x == 0) any = 0;
    __syncthreads();
    int acc = 0;
    for (int i = threadIdx.x; i < 4096; i += 256)
        acc |= ei32[2 * i + 1];          // high words if int64; real data if int32
    if (acc) atomicOr(&any, 1);
    __syncthreads();
    if (threadIdx.x == 0) g_stride = any ? 1 : 2;
}

// ---------------- CSR build ----------------
__global__ void k_zero_deg() {
    int i = blockIdx.x * blockDim.x + threadIdx.x;
    if (i < NN) g_deg[i] = 0;
}

__global__ void k_count(const int* __restrict__ ei) {
    int i = blockIdx.x * blockDim.x + threadIdx.x;
    if (i >= EP) return;
    int st = g_stride;
    int dst = (i < EE) ? clampN(ei[(size_t)(EE + i) * st]) : (i - EE);
    atomicAdd(&g_deg[dst], 1);
}

__global__ void k_scan1() {
    __shared__ int s[128];
    int i = blockIdx.x * 128 + threadIdx.x;
    s[threadIdx.x] = (i < NN) ? g_deg[i] : 0;
    __syncthreads();
    for (int off = 64; off; off >>= 1) {
        if (threadIdx.x < off) s[threadIdx.x] += s[threadIdx.x + off];
        __syncthreads();
    }
    if (threadIdx.x == 0) g_part[blockIdx.x] = s[0];
}

__global__ void k_scan2() {
    __shared__ int s[1024];
    int t = threadIdx.x;
    int v = (t < NBLK) ? g_part[t] : 0;
    s[t] = v;
    __syncthreads();
    for (int off = 1; off < 1024; off <<= 1) {
        int a = (t >= off) ? s[t - off] : 0;
        __syncthreads();
        s[t] += a;
        __syncthreads();
    }
    if (t < NBLK) g_pscan[t] = s[t] - v;   // exclusive
}

__global__ void k_scan3() {
    __shared__ int s[128];
    int t = threadIdx.x;
    int i = blockIdx.x * 128 + t;
    int v = (i < NN) ? g_deg[i] : 0;
    s[t] = v;
    __syncthreads();
    for (int off = 1; off < 128; off <<= 1) {
        int a = (t >= off) ? s[t - off] : 0;
        __syncthreads();
        s[t] += a;
        __syncthreads();
    }
    int excl = s[t] - v + g_pscan[blockIdx.x];
    if (i < NN) {
        g_rowptr[i] = excl;
        g_cursor[i] = excl;
        if (i == NN - 1) g_rowptr[NN] = excl + v;
    }
}

__global__ void k_fill(const int* __restrict__ ei) {
    int i = blockIdx.x * blockDim.x + threadIdx.x;
    if (i >= EP) return;
    int st = g_stride;
    int src, dst;
    if (i < EE) {
        src = clampN(ei[(size_t)i * st]);
        dst = clampN(ei[(size_t)(EE + i) * st]);
    } else {
        src = i - EE; dst = i - EE;
    }
    int pos = atomicAdd(&g_cursor[dst], 1);
    if (pos >= 0 && pos < EP) g_csr[pos] = src;
}

// ---------------- feature transform: h = x@W ; asrc/adst = head dots --------
template <int DINT>
__global__ void k_feat(const float* __restrict__ xin_param,
                       const float* __restrict__ W,
                       const float* __restrict__ avs,
                       const float* __restrict__ avd) {
    __shared__ float sW[DINT * 64];
    __shared__ float sx[4][DINT];
    const float* xin = (DINT == 32) ? xin_param : g_hB;
    int base = blockIdx.x * 4;
    for (int i = threadIdx.x; i < DINT * 64; i += 256) sW[i] = W[i];
    for (int i = threadIdx.x; i < 4 * DINT; i += 256) {
        int nl = i / DINT, c = i % DINT;
        int nd = base + nl;
        sx[nl][c] = (nd < NN) ? xin[(size_t)nd * DINT + c] : 0.f;
    }
    __syncthreads();
    int nl = threadIdx.x >> 6;
    int ch = threadIdx.x & 63;
    int node = base + nl;
    float acc = 0.f;
#pragma unroll
    for (int k = 0; k < DINT; k++) acc += sx[nl][k] * sW[k * 64 + ch];
    if (node < NN) g_hA[(size_t)node * HC + ch] = acc;
    // per-head reductions over 16-lane groups (offsets 8,4,2,1)
    float va = acc * avs[ch];
    float vd = acc * avd[ch];
#pragma unroll
    for (int off = 8; off; off >>= 1) {
        va += __shfl_xor_sync(0xffffffffu, va, off);
        vd += __shfl_xor_sync(0xffffffffu, vd, off);
    }
    if ((ch & 15) == 0 && node < NN) {
        int head = ch >> 4;
        g_asrc[node * 4 + head] = va;
        g_adst[node * 4 + head] = vd;
    }
}

// ---------------- GAT aggregation: warp per dst node ----------------
// softmax without max-subtraction (logits bounded ~O(1) for this data scale)
__global__ void k_gat(const float* __restrict__ bias) {
    int wid = (blockIdx.x * blockDim.x + threadIdx.x) >> 5;
    if (wid >= NN) return;
    int lane = threadIdx.x & 31;
    int row = g_rowptr[wid], end = g_rowptr[wid + 1];
    float adl = (lane < 4) ? g_adst[wid * 4 + lane] : 0.f;
    float acx = 0.f, acy = 0.f, den = 0.f;
    int myh = lane >> 3;   // lane k owns channels 2k,2k+1 -> head k/8
    for (int j = row; j < end; ++j) {
        int s = g_csr[j];
        float ex = 0.f;
        if (lane < 4) {
            float v = g_asrc[s * 4 + lane] + adl;
            float e = v > 0.f ? v : 0.2f * v;       // leaky_relu(0.2)
            ex = __expf(e);
            den += ex;
        }
        float exk = __shfl_sync(0xffffffffu, ex, myh);
        float2 hv = *(const float2*)&g_hA[(size_t)s * HC + (lane << 1)];
        acx += exk * hv.x;
        acy += exk * hv.y;
    }
    float dh = __shfl_sync(0xffffffffu, den, myh);
    float inv = 1.f / dh;
    int ch = lane << 1;
    float o0 = acx * inv + bias[ch];
    float o1 = acy * inv + bias[ch + 1];
    o0 = o0 > 0.f ? o0 : expm1f(o0);                // elu
    o1 = o1 > 0.f ? o1 : expm1f(o1);
    g_hB[(size_t)wid * HC + ch]     = o0;
    g_hB[(size_t)wid * HC + ch + 1] = o1;
}

// ---------------- pooling + head ----------------
__global__ void k_zero_pool() {
    int i = blockIdx.x * blockDim.x + threadIdx.x;
    if (i < GG * HC) g_pool[i] = 0.f;
    if (i < GG) g_cnt[i] = 0;
}

__global__ void k_pool(const int* __restrict__ batch) {
    int i = blockIdx.x * blockDim.x + threadIdx.x;
    if (i >= NN * HC) return;
    int node = i >> 6, ch = i & 63;
    int st = g_stride;
    int gph = batch[(size_t)node * st];
    gph = gph < 0 ? 0 : (gph >= GG ? GG - 1 : gph);
    atomicAdd(&g_pool[gph * HC + ch], g_hB[i]);
    if (ch == 0) atomicAdd(&g_cnt[gph], 1);
}

__global__ void k_head(const float* __restrict__ guidance,
                       const float* __restrict__ Wg, const float* __restrict__ bg,
                       const float* __restrict__ Wu, const float* __restrict__ bu,
                       const float* __restrict__ Wo, const float* __restrict__ bo,
                       float* __restrict__ out) {
    int wid = (blockIdx.x * blockDim.x + threadIdx.x) >> 5;
    if (wid >= GG) return;
    int lane = threadIdx.x & 31;
    float cnt = fmaxf((float)g_cnt[wid], 1.f);
    float t = 0.f;
    if (lane < 16) {
        float acc = 0.f;
#pragma unroll
        for (int k = 0; k < HC; k++)
            acc += g_pool[wid * HC + k] * Wg[k * 16 + lane];
        acc = acc / cnt + bg[lane];
        float xu = guidance[wid] * Wu[lane] + bu[lane];
        xu = fmaxf(xu, 0.f);
        t = acc + xu;
    }
    float o = (lane < 7) ? bo[lane] : 0.f;
#pragma unroll
    for (int c = 0; c < 16; c++) {
        float v = __shfl_sync(0xffffffffu, t, c);
        if (lane < 7) o += v * Wo[c * 7 + lane];
    }
    if (lane < 7) out[wid * 7 + lane] = o;
}

// ---------------- launch ----------------
extern "C" void kernel_launch(void* const* d_in, const int* in_sizes, int n_in,
                              void* d_out, int out_size) {
    const float* x   = (const float*)d_in[0];
    const int*   ei  = (const int*)d_in[1];
    const int*   bat = (const int*)d_in[2];
    const float* gui = (const float*)d_in[3];
    const float* W1  = (const float*)d_in[4];
    const float* as1 = (const float*)d_in[5];
    const float* ad1 = (const float*)d_in[6];
    const float* b1  = (const float*)d_in[7];
    const float* W2  = (const float*)d_in[8];
    const float* as2 = (const float*)d_in[9];
    const float* ad2 = (const float*)d_in[10];
    const float* b2  = (const float*)d_in[11];
    const float* Wg  = (const float*)d_in[12];
    const float* bg  = (const float*)d_in[13];
    const float* Wu  = (const float*)d_in[14];
    const float* bu  = (const float*)d_in[15];
    const float* Wo  = (const float*)d_in[16];
    const float* bo  = (const float*)d_in[17];
    float* out = (float*)d_out;

    // index dtype probe, then CSR build (reused by both layers)
    k_detect<<<1, 256>>>(ei);
    k_zero_deg<<<(NN + 255) / 256, 256>>>();
    k_count<<<(EP + 255) / 256, 256>>>(ei);
    k_scan1<<<NBLK, 128>>>();
    k_scan2<<<1, 1024>>>();
    k_scan3<<<NBLK, 128>>>();
    k_fill<<<(EP + 255) / 256, 256>>>(ei);

    // layer 1
    k_feat<32><<<(NN + 3) / 4, 256>>>(x, W1, as1, ad1);
    k_gat<<<(NN + 7) / 8, 256>>>(b1);
    // layer 2
    k_feat<64><<<(NN + 3) / 4, 256>>>(nullptr, W2, as2, ad2);
    k_gat<<<(NN + 7) / 8, 256>>>(b2);

    // pool + head
    k_zero_pool<<<(GG * HC + 255) / 256, 256>>>();
    k_pool<<<(NN * HC + 255) / 256, 256>>>(bat);
    k_head<<<(GG + 7) / 8, 256>>>(gui, Wg, bg, Wu, bu, Wo, bo, out);
}

// round 3
// speedup vs baseline: 1.1127x; 1.1127x over previous
#include <cuda_runtime.h>
#include <cuda_fp16.h>
#include <math.h>

#define NN 100000
#define EE 3200000
#define EP (EE + NN)
#define GG 1024
#define HC 64
#define NBLK ((NN + 127) / 128)

// ---------------- device scratch (no allocations allowed) ----------------
__device__ int    g_stride;        // 1 if indices are int32, 2 if int64
__device__ int    g_deg[NN];
__device__ int    g_rowptr[NN + 1];
__device__ int    g_cursor[NN];
__device__ int    g_csr[EP];
__device__ int    g_part[NBLK];
__device__ int    g_pscan[NBLK];
__device__ __half g_hAh[NN * HC];  // pre-aggregation features (x@W), fp16 for gather BW
__device__ float  g_hB[NN * HC];   // post-aggregation (elu) features, fp32
__device__ float  g_asrc[NN * 4];
__device__ float  g_adst[NN * 4];
__device__ float  g_pool[GG * HC];
__device__ int    g_cnt[GG];

__device__ __forceinline__ int clampN(int v) {
    return v < 0 ? 0 : (v >= NN ? NN - 1 : v);
}

// ---------------- dtype probe: int32 vs int64 index buffers ----------------
__global__ void k_detect(const int* __restrict__ ei32) {
    __shared__ int any;
    if (threadIdx.x == 0) any = 0;
    __syncthreads();
    int acc = 0;
    for (int i = threadIdx.x; i < 4096; i += 256)
        acc |= ei32[2 * i + 1];          // high words if int64; real data if int32
    if (acc) atomicOr(&any, 1);
    __syncthreads();
    if (threadIdx.x == 0) g_stride = any ? 1 : 2;
}

// ---------------- CSR build ----------------
__global__ void k_zero_deg() {
    int i = blockIdx.x * blockDim.x + threadIdx.x;
    if (i < NN) g_deg[i] = 0;
}

__global__ void k_count(const int* __restrict__ ei) {
    int i = blockIdx.x * blockDim.x + threadIdx.x;
    if (i >= EP) return;
    int st = g_stride;
    int dst = (i < EE) ? clampN(ei[(size_t)(EE + i) * st]) : (i - EE);
    atomicAdd(&g_deg[dst], 1);
}

__global__ void k_scan1() {
    __shared__ int s[128];
    int i = blockIdx.x * 128 + threadIdx.x;
    s[threadIdx.x] = (i < NN) ? g_deg[i] : 0;
    __syncthreads();
    for (int off = 64; off; off >>= 1) {
        if (threadIdx.x < off) s[threadIdx.x] += s[threadIdx.x + off];
        __syncthreads();
    }
    if (threadIdx.x == 0) g_part[blockIdx.x] = s[0];
}

__global__ void k_scan2() {
    __shared__ int s[1024];
    int t = threadIdx.x;
    int v = (t < NBLK) ? g_part[t] : 0;
    s[t] = v;
    __syncthreads();
    for (int off = 1; off < 1024; off <<= 1) {
        int a = (t >= off) ? s[t - off] : 0;
        __syncthreads();
        s[t] += a;
        __syncthreads();
    }
    if (t < NBLK) g_pscan[t] = s[t] - v;   // exclusive
}

__global__ void k_scan3() {
    __shared__ int s[128];
    int t = threadIdx.x;
    int i = blockIdx.x * 128 + t;
    int v = (i < NN) ? g_deg[i] : 0;
    s[t] = v;
    __syncthreads();
    for (int off = 1; off < 128; off <<= 1) {
        int a = (t >= off) ? s[t - off] : 0;
        __syncthreads();
        s[t] += a;
        __syncthreads();
    }
    int excl = s[t] - v + g_pscan[blockIdx.x];
    if (i < NN) {
        g_rowptr[i] = excl;
        g_cursor[i] = excl;
        if (i == NN - 1) g_rowptr[NN] = excl + v;
    }
}

__global__ void k_fill(const int* __restrict__ ei) {
    int i = blockIdx.x * blockDim.x + threadIdx.x;
    if (i >= EP) return;
    int st = g_stride;
    int src, dst;
    if (i < EE) {
        src = clampN(ei[(size_t)i * st]);
        dst = clampN(ei[(size_t)(EE + i) * st]);
    } else {
        src = i - EE; dst = i - EE;
    }
    int pos = atomicAdd(&g_cursor[dst], 1);
    if (pos >= 0 && pos < EP) g_csr[pos] = src;
}

// ---------------- feature transform: h = x@W ; asrc/adst = head dots --------
// 4 nodes per 256-thread block; 64 threads per node, one output channel each.
template <int DINT>
__global__ void k_feat(const float* __restrict__ xin_param,
                       const float* __restrict__ W,
                       const float* __restrict__ avs,
                       const float* __restrict__ avd) {
    __shared__ float sW[DINT * 64];
    __shared__ float sx[4][DINT];
    const float* xin = (DINT == 32) ? xin_param : g_hB;
    int base = blockIdx.x * 4;
    for (int i = threadIdx.x; i < DINT * 64; i += 256) sW[i] = W[i];
    for (int i = threadIdx.x; i < 4 * DINT; i += 256) {
        int nl = i / DINT, c = i % DINT;
        int nd = base + nl;
        sx[nl][c] = (nd < NN) ? xin[(size_t)nd * DINT + c] : 0.f;
    }
    __syncthreads();
    int nl = threadIdx.x >> 6;
    int ch = threadIdx.x & 63;
    int node = base + nl;
    float acc = 0.f;
#pragma unroll
    for (int k = 0; k < DINT; k++) acc += sx[nl][k] * sW[k * 64 + ch];
    if (node < NN) g_hAh[(size_t)node * HC + ch] = __float2half_rn(acc);
    // per-head reductions over 16-lane groups (offsets 8,4,2,1) — fp32, pre-quantization
    float va = acc * avs[ch];
    float vd = acc * avd[ch];
#pragma unroll
    for (int off = 8; off; off >>= 1) {
        va += __shfl_xor_sync(0xffffffffu, va, off);
        vd += __shfl_xor_sync(0xffffffffu, vd, off);
    }
    if ((ch & 15) == 0 && node < NN) {
        int head = ch >> 4;
        g_asrc[node * 4 + head] = va;
        g_adst[node * 4 + head] = vd;
    }
}

// ---------------- GAT aggregation: half-warp per dst node ----------------
// 2 dst nodes per warp; lane owns 4 channels (one 8B fp16 load per edge).
// softmax without max-subtraction (logits bounded ~O(1) for this data scale).
__global__ void k_gat(const float* __restrict__ bias) {
    int gwarp = (blockIdx.x * blockDim.x + threadIdx.x) >> 5;
    if (gwarp * 2 >= NN) return;               // NN even: whole warp exits together
    int lane = threadIdx.x & 31;
    int grp  = lane >> 4;                      // 0 or 1: which dst this half-warp owns
    int lg   = lane & 15;
    int node = gwarp * 2 + grp;
    int row = g_rowptr[node], end = g_rowptr[node + 1];
    int deg = end - row;
    int odeg = __shfl_xor_sync(0xffffffffu, deg, 16);
    int tmax = max(deg, odeg);                 // uniform trip count for the warp
    float adl = (lg < 4) ? g_adst[node * 4 + lg] : 0.f;
    float a0 = 0.f, a1 = 0.f, a2 = 0.f, a3 = 0.f, den = 0.f;
    int srcl = (grp << 4) + (lg >> 2);         // lane holding exp() for my head
#pragma unroll 2
    for (int jj = 0; jj < tmax; ++jj) {
        bool act = jj < deg;
        int s = g_csr[act ? row + jj : row];
        float ex = 0.f;
        if (act && lg < 4) {
            float v = g_asrc[s * 4 + lg] + adl;
            float e = v > 0.f ? v : 0.2f * v;  // leaky_relu(0.2)
            ex = __expf(e);
            den += ex;
        }
        float exk = __shfl_sync(0xffffffffu, ex, srcl);
        uint2 hraw = *(const uint2*)(g_hAh + (size_t)s * HC + (lg << 2));
        __half2 h01 = *reinterpret_cast<__half2*>(&hraw.x);
        __half2 h23 = *reinterpret_cast<__half2*>(&hraw.y);
        float2 p0 = __half22float2(h01);
        float2 p1 = __half22float2(h23);
        a0 += exk * p0.x; a1 += exk * p0.y;
        a2 += exk * p1.x; a3 += exk * p1.y;
    }
    float dh = __shfl_sync(0xffffffffu, den, srcl);
    float inv = 1.f / dh;
    int ch = lg << 2;
    float o0 = a0 * inv + bias[ch];
    float o1 = a1 * inv + bias[ch + 1];
    float o2 = a2 * inv + bias[ch + 2];
    float o3 = a3 * inv + bias[ch + 3];
    o0 = o0 > 0.f ? o0 : expm1f(o0);           // elu
    o1 = o1 > 0.f ? o1 : expm1f(o1);
    o2 = o2 > 0.f ? o2 : expm1f(o2);
    o3 = o3 > 0.f ? o3 : expm1f(o3);
    *(float4*)&g_hB[(size_t)node * HC + ch] = make_float4(o0, o1, o2, o3);
}

// ---------------- pooling + head ----------------
__global__ void k_zero_pool() {
    int i = blockIdx.x * blockDim.x + threadIdx.x;
    if (i < GG * HC) g_pool[i] = 0.f;
    if (i < GG) g_cnt[i] = 0;
}

__global__ void k_pool(const int* __restrict__ batch) {
    int i = blockIdx.x * blockDim.x + threadIdx.x;
    if (i >= NN * HC) return;
    int node = i >> 6, ch = i & 63;
    int st = g_stride;
    int gph = batch[(size_t)node * st];
    gph = gph < 0 ? 0 : (gph >= GG ? GG - 1 : gph);
    atomicAdd(&g_pool[gph * HC + ch], g_hB[i]);
    if (ch == 0) atomicAdd(&g_cnt[gph], 1);
}

__global__ void k_head(const float* __restrict__ guidance,
                       const float* __restrict__ Wg, const float* __restrict__ bg,
                       const float* __restrict__ Wu, const float* __restrict__ bu,
                       const float* __restrict__ Wo, const float* __restrict__ bo,
                       float* __restrict__ out) {
    int wid = (blockIdx.x * blockDim.x + threadIdx.x) >> 5;
    if (wid >= GG) return;
    int lane = threadIdx.x & 31;
    float cnt = fmaxf((float)g_cnt[wid], 1.f);
    float t = 0.f;
    if (lane < 16) {
        float acc = 0.f;
#pragma unroll
        for (int k = 0; k < HC; k++)
            acc += g_pool[wid * HC + k] * Wg[k * 16 + lane];
        acc = acc / cnt + bg[lane];
        float xu = guidance[wid] * Wu[lane] + bu[lane];
        xu = fmaxf(xu, 0.f);
        t = acc + xu;
    }
    float o = (lane < 7) ? bo[lane] : 0.f;
#pragma unroll
    for (int c = 0; c < 16; c++) {
        float v = __shfl_sync(0xffffffffu, t, c);
        if (lane < 7) o += v * Wo[c * 7 + lane];
    }
    if (lane < 7) out[wid * 7 + lane] = o;
}

// ---------------- launch ----------------
extern "C" void kernel_launch(void* const* d_in, const int* in_sizes, int n_in,
                              void* d_out, int out_size) {
    const float* x   = (const float*)d_in[0];
    const int*   ei  = (const int*)d_in[1];
    const int*   bat = (const int*)d_in[2];
    const float* gui = (const float*)d_in[3];
    const float* W1  = (const float*)d_in[4];
    const float* as1 = (const float*)d_in[5];
    const float* ad1 = (const float*)d_in[6];
    const float* b1  = (const float*)d_in[7];
    const float* W2  = (const float*)d_in[8];
    const float* as2 = (const float*)d_in[9];
    const float* ad2 = (const float*)d_in[10];
    const float* b2  = (const float*)d_in[11];
    const float* Wg  = (const float*)d_in[12];
    const float* bg  = (const float*)d_in[13];
    const float* Wu  = (const float*)d_in[14];
    const float* bu  = (const float*)d_in[15];
    const float* Wo  = (const float*)d_in[16];
    const float* bo  = (const float*)d_in[17];
    float* out = (float*)d_out;

    // index dtype probe, then CSR build (reused by both layers)
    k_detect<<<1, 256>>>(ei);
    k_zero_deg<<<(NN + 255) / 256, 256>>>();
    k_count<<<(EP + 255) / 256, 256>>>(ei);
    k_scan1<<<NBLK, 128>>>();
    k_scan2<<<1, 1024>>>();
    k_scan3<<<NBLK, 128>>>();
    k_fill<<<(EP + 255) / 256, 256>>>(ei);

    // layer 1
    k_feat<32><<<(NN + 3) / 4, 256>>>(x, W1, as1, ad1);
    k_gat<<<(NN / 2 + 7) / 8, 256>>>(b1);
    // layer 2
    k_feat<64><<<(NN + 3) / 4, 256>>>(nullptr, W2, as2, ad2);
    k_gat<<<(NN / 2 + 7) / 8, 256>>>(b2);

    // pool + head
    k_zero_pool<<<(GG * HC + 255) / 256, 256>>>();
    k_pool<<<(NN * HC + 255) / 256, 256>>>(bat);
    k_head<<<(GG + 7) / 8, 256>>>(gui, Wg, bg, Wu, bu, Wo, bo, out);
}